// round 5
// baseline (speedup 1.0000x reference)
#include <cuda_runtime.h>
#include <cuda_bf16.h>
#include <cstdint>

#define NN 50000
#define NE 600000
#define NG 500
#define F  128

// ---------------- scratch (static __device__, no allocation) ----------------
__device__ __align__(16) float g_T [NN * F];   // t = h_in @ W (raw, pre-normalization)
__device__ __align__(16) float g_H0[NN * F];   // layer outputs (ping)
__device__ __align__(16) float g_H1[NN * F];   // layer outputs (pong)
__device__ int   g_degi[NN];
__device__ float g_dinv[NN];
__device__ int   g_s32[NE];
__device__ int   g_d32[NE];
__device__ float g_norm[NE];
__device__ __align__(16) float g_sums[NG * F];
__device__ int   g_cnt [NG];
__device__ int   g_e64;   // 1 if edge_index is int64, 0 if int32
__device__ int   g_b64;   // 1 if batch is int64, 0 if int32

// ---------------- dtype detection (int64 vs silently-downcast int32) ----------------
__global__ void k_detect(const void* edge, const void* batch) {
    if (threadIdx.x != 0 || blockIdx.x != 0) return;
    const long long* e64 = (const long long*)edge;
    int ok = 1;
    for (int i = 0; i < 256; i++) {
        long long v = e64[i];
        if (v < 0 || v >= NN) { ok = 0; break; }
    }
    g_e64 = ok;
    const long long* b64 = (const long long*)batch;
    ok = 1;
    for (int i = 0; i < 256; i++) {
        long long v = b64[i];
        if (v < 0 || v >= NG) { ok = 0; break; }
    }
    g_b64 = ok;
}

__device__ __forceinline__ int edge_at(const void* edge, long long idx) {
    return g_e64 ? (int)((const long long*)edge)[idx] : ((const int*)edge)[idx];
}
__device__ __forceinline__ int batch_at(const void* batch, int idx) {
    return g_b64 ? (int)((const long long*)batch)[idx] : ((const int*)batch)[idx];
}

// ---------------- prep kernels ----------------
__global__ void k_zero() {
    int i = blockIdx.x * blockDim.x + threadIdx.x;
    if (i < NN) g_degi[i] = 0;
    if (i < NG * F) g_sums[i] = 0.f;
    if (i < NG) g_cnt[i] = 0;
}

__global__ void k_deg(const void* __restrict__ edge) {
    int i = blockIdx.x * blockDim.x + threadIdx.x;
    if (i >= NE) return;
    int d = edge_at(edge, (long long)NE + i);
    if (d >= 0 && d < NN) atomicAdd(&g_degi[d], 1);
}

__global__ void k_dinv() {
    int i = blockIdx.x * blockDim.x + threadIdx.x;
    if (i >= NN) return;
    g_dinv[i] = rsqrtf((float)(g_degi[i] + 1));   // +1 self loop
}

__global__ void k_prep(const void* __restrict__ edge) {
    int i = blockIdx.x * blockDim.x + threadIdx.x;
    if (i >= NE) return;
    int s = edge_at(edge, i);
    int d = edge_at(edge, (long long)NE + i);
    g_s32[i] = s;
    g_d32[i] = d;
    g_norm[i] = g_dinv[s] * g_dinv[d];
}

// ---------------- SGEMM: C[M,128] = (relu?)A[M,128] @ W[128,128] ----------------
// SRC: 0 = external pointer (x), 1 = g_H0, 2 = g_H1 ; DST: 1 = g_H0, 2 = g_H1
// Writes: g_T = raw product; g_Hdst = T * dinv[row]^2 + b[col]  (self-loop + bias init)
template<bool RELU_IN, int SRC, int DST>
__global__ void __launch_bounds__(256) k_gemm(const float* __restrict__ Aext,
                                              const float* __restrict__ W,
                                              const float* __restrict__ b) {
    const float* A = (SRC == 0) ? Aext : (SRC == 1 ? (const float*)g_H0 : (const float*)g_H1);
    float* O = (DST == 1) ? g_H0 : g_H1;

    __shared__ float As[8][128];
    __shared__ float Bs[8][128];
    __shared__ float bias[128];
    const int tid = threadIdx.x;          // 256 threads
    const int blockRow = blockIdx.x * 128;
    const int ty = tid >> 4;              // 0..15
    const int tx = tid & 15;              // 0..15

    const int a_r = tid >> 1;             // 0..127
    const int a_c = (tid & 1) * 4;        // 0 or 4
    const int b_r = tid >> 5;             // 0..7
    const int b_c = (tid & 31) * 4;       // 0..124

    if (tid < 128) bias[tid] = b[tid];

    float acc[8][8];
#pragma unroll
    for (int i = 0; i < 8; i++)
#pragma unroll
        for (int j = 0; j < 8; j++) acc[i][j] = 0.f;

    for (int k0 = 0; k0 < 128; k0 += 8) {
        float4 av = make_float4(0.f, 0.f, 0.f, 0.f);
        int gr = blockRow + a_r;
        if (gr < NN) av = *(const float4*)(A + (size_t)gr * 128 + k0 + a_c);
        if (RELU_IN) {
            av.x = fmaxf(av.x, 0.f); av.y = fmaxf(av.y, 0.f);
            av.z = fmaxf(av.z, 0.f); av.w = fmaxf(av.w, 0.f);
        }
        As[a_c + 0][a_r] = av.x;
        As[a_c + 1][a_r] = av.y;
        As[a_c + 2][a_r] = av.z;
        As[a_c + 3][a_r] = av.w;

        *(float4*)&Bs[b_r][b_c] = *(const float4*)(W + (size_t)(k0 + b_r) * 128 + b_c);
        __syncthreads();

#pragma unroll
        for (int k = 0; k < 8; k++) {
            float4 ra0 = *(const float4*)&As[k][ty * 8];
            float4 ra1 = *(const float4*)&As[k][ty * 8 + 4];
            float4 rb0 = *(const float4*)&Bs[k][tx * 8];
            float4 rb1 = *(const float4*)&Bs[k][tx * 8 + 4];
            float ra[8] = {ra0.x, ra0.y, ra0.z, ra0.w, ra1.x, ra1.y, ra1.z, ra1.w};
            float rb[8] = {rb0.x, rb0.y, rb0.z, rb0.w, rb1.x, rb1.y, rb1.z, rb1.w};
#pragma unroll
            for (int i = 0; i < 8; i++)
#pragma unroll
                for (int j = 0; j < 8; j++) acc[i][j] = fmaf(ra[i], rb[j], acc[i][j]);
        }
        __syncthreads();
    }

#pragma unroll
    for (int i = 0; i < 8; i++) {
        int r = blockRow + ty * 8 + i;
        if (r >= NN) continue;
        float dv = g_dinv[r];
        float d2 = dv * dv;
#pragma unroll
        for (int j = 0; j < 8; j++) {
            int c = tx * 8 + j;
            float t = acc[i][j];
            g_T[(size_t)r * 128 + c] = t;
            O[(size_t)r * 128 + c] = fmaf(t, d2, bias[c]);
        }
    }
}

// ---------------- edge scatter: O[d] += T[s] * norm[e]  (1 warp / edge) ----------------
template<int DST>
__global__ void __launch_bounds__(256) k_scatter() {
    float* O = (DST == 1) ? g_H0 : g_H1;
    int gw = (blockIdx.x * blockDim.x + threadIdx.x) >> 5;
    int lane = threadIdx.x & 31;
    if (gw >= NE) return;
    int s = g_s32[gw];
    int d = g_d32[gw];
    float w = g_norm[gw];
    float4 v = *(const float4*)(g_T + (size_t)s * 128 + lane * 4);
    float* p = O + (size_t)d * 128 + lane * 4;
    atomicAdd(p + 0, v.x * w);
    atomicAdd(p + 1, v.y * w);
    atomicAdd(p + 2, v.z * w);
    atomicAdd(p + 3, v.w * w);
}

// ---------------- pooling: sums[batch[i]] += relu(H0[i]) ----------------
__global__ void __launch_bounds__(256) k_pool(const void* __restrict__ batch) {
    int node = (blockIdx.x * blockDim.x + threadIdx.x) >> 5;
    int lane = threadIdx.x & 31;
    if (node >= NN) return;
    int g = batch_at(batch, node);
    float4 v = *(const float4*)(g_H0 + (size_t)node * 128 + lane * 4);
    float* p = g_sums + g * 128 + lane * 4;
    atomicAdd(p + 0, fmaxf(v.x, 0.f));
    atomicAdd(p + 1, fmaxf(v.y, 0.f));
    atomicAdd(p + 2, fmaxf(v.z, 0.f));
    atomicAdd(p + 3, fmaxf(v.w, 0.f));
    if (lane == 0) atomicAdd(&g_cnt[g], 1);
}

// ---------------- head: out[g] = relu(mean @ Wf1 + bf1) @ Wf2 + bf2 ----------------
__global__ void __launch_bounds__(64) k_head(const float* __restrict__ Wf1,
                                             const float* __restrict__ bf1,
                                             const float* __restrict__ Wf2,
                                             const float* __restrict__ bf2,
                                             float* __restrict__ out) {
    int g = blockIdx.x;
    int j = threadIdx.x;          // 0..63
    __shared__ float hg[128];
    __shared__ float red[2];
    float invc = 1.f / fmaxf((float)g_cnt[g], 1.f);
    for (int k = j; k < 128; k += 64) hg[k] = g_sums[g * 128 + k] * invc;
    __syncthreads();
    float acc = bf1[j];
#pragma unroll
    for (int k = 0; k < 128; k++) acc = fmaf(hg[k], Wf1[k * 64 + j], acc);
    acc = fmaxf(acc, 0.f) * Wf2[j];
#pragma unroll
    for (int off = 16; off; off >>= 1) acc += __shfl_down_sync(0xffffffffu, acc, off);
    if ((j & 31) == 0) red[j >> 5] = acc;
    __syncthreads();
    if (j == 0) out[g] = red[0] + red[1] + bf2[0];
}

// ---------------- launch ----------------
extern "C" void kernel_launch(void* const* d_in, const int* in_sizes, int n_in,
                              void* d_out, int out_size) {
    const float* x    = (const float*)d_in[0];
    const void*  edge = d_in[1];
    const void*  bat  = d_in[2];
    const float* W1 = (const float*)d_in[3];
    const float* b1 = (const float*)d_in[4];
    const float* W2 = (const float*)d_in[5];
    const float* b2 = (const float*)d_in[6];
    const float* W3 = (const float*)d_in[7];
    const float* b3 = (const float*)d_in[8];
    const float* Wf1 = (const float*)d_in[9];
    const float* bf1 = (const float*)d_in[10];
    const float* Wf2 = (const float*)d_in[11];
    const float* bf2 = (const float*)d_in[12];
    float* out = (float*)d_out;

    const int TPB = 256;
    k_detect<<<1, 32>>>(edge, bat);
    k_zero<<<(NG * F + TPB - 1) / TPB, TPB>>>();
    k_deg <<<(NE + TPB - 1) / TPB, TPB>>>(edge);
    k_dinv<<<(NN + TPB - 1) / TPB, TPB>>>();
    k_prep<<<(NE + TPB - 1) / TPB, TPB>>>(edge);

    const int gemmGrid = (NN + 127) / 128;
    const int scatGrid = (int)(((long long)NE * 32 + TPB - 1) / TPB);

    // layer 1: x -> H0
    k_gemm<false, 0, 1><<<gemmGrid, 256>>>(x, W1, b1);
    k_scatter<1><<<scatGrid, TPB>>>();
    // layer 2: H0 -> H1
    k_gemm<true, 1, 2><<<gemmGrid, 256>>>(nullptr, W2, b2);
    k_scatter<2><<<scatGrid, TPB>>>();
    // layer 3: H1 -> H0
    k_gemm<true, 2, 1><<<gemmGrid, 256>>>(nullptr, W3, b3);
    k_scatter<1><<<scatGrid, TPB>>>();

    // pool + head
    k_pool<<<(int)(((long long)NN * 32 + TPB - 1) / TPB), TPB>>>(bat);
    k_head<<<NG, 64>>>(Wf1, bf1, Wf2, bf2, out);
}

// round 9
// speedup vs baseline: 2.3350x; 2.3350x over previous
#include <cuda_runtime.h>
#include <cuda_bf16.h>
#include <cstdint>

#define NN 50000
#define NE 600000
#define NG 500
#define F  128
#define NB 196   // (NN+255)/256

// ---------------- scratch (static __device__, no allocation) ----------------
__device__ __align__(16) float g_T [NN * F];   // t = h_in @ W (raw)
__device__ __align__(16) float g_H0[NN * F];   // layer outputs (ping)
__device__ __align__(16) float g_H1[NN * F];   // layer outputs (pong)
__device__ int   g_degi[NN];
__device__ float g_dinv[NN];
__device__ int   g_tmp [NN];
__device__ int   g_bsum[256];
__device__ int   g_boff[256];
__device__ int   g_start[NN];
__device__ int   g_cur [NN];
__device__ int   g_csrc[NE];
__device__ float g_cw  [NE];
__device__ __align__(16) float g_sums[NG * F];
__device__ int   g_cnt [NG];
__device__ int   g_e64;   // 1 if edge_index is int64, 0 if int32
__device__ int   g_b64;   // 1 if batch is int64, 0 if int32

// ---------------- dtype detection (int64 vs silently-downcast int32) ----------------
__global__ void k_detect(const void* edge, const void* batch) {
    if (threadIdx.x != 0 || blockIdx.x != 0) return;
    const long long* e64 = (const long long*)edge;
    int ok = 1;
    for (int i = 0; i < 256; i++) {
        long long v = e64[i];
        if (v < 0 || v >= NN) { ok = 0; break; }
    }
    g_e64 = ok;
    const long long* b64 = (const long long*)batch;
    ok = 1;
    for (int i = 0; i < 256; i++) {
        long long v = b64[i];
        if (v < 0 || v >= NG) { ok = 0; break; }
    }
    g_b64 = ok;
}

__device__ __forceinline__ int edge_at(const void* edge, long long idx) {
    return g_e64 ? (int)((const long long*)edge)[idx] : ((const int*)edge)[idx];
}
__device__ __forceinline__ int batch_at(const void* batch, int idx) {
    return g_b64 ? (int)((const long long*)batch)[idx] : ((const int*)batch)[idx];
}

// ---------------- prep ----------------
__global__ void k_zero() {
    int i = blockIdx.x * blockDim.x + threadIdx.x;
    if (i < NN) g_degi[i] = 0;
    if (i < NG * F) g_sums[i] = 0.f;
    if (i < NG) g_cnt[i] = 0;
}

__global__ void k_deg(const void* __restrict__ edge) {
    int i = blockIdx.x * blockDim.x + threadIdx.x;
    if (i >= NE) return;
    int d = edge_at(edge, (long long)NE + i);
    atomicAdd(&g_degi[d], 1);
}

__global__ void k_dinv() {
    int i = blockIdx.x * blockDim.x + threadIdx.x;
    if (i >= NN) return;
    g_dinv[i] = rsqrtf((float)(g_degi[i] + 1));   // +1 self loop
}

// ---- 3-kernel exclusive prefix sum over g_degi -> g_start ----
__global__ void k_scan1() {
    __shared__ int s[256];
    int b = blockIdx.x, t = threadIdx.x;
    int i = b * 256 + t;
    int v = (i < NN) ? g_degi[i] : 0;
    s[t] = v; __syncthreads();
#pragma unroll
    for (int off = 1; off < 256; off <<= 1) {
        int x = 0;
        if (t >= off) x = s[t - off];
        __syncthreads();
        if (t >= off) s[t] += x;
        __syncthreads();
    }
    if (i < NN) g_tmp[i] = s[t];        // inclusive within block
    if (t == 255) g_bsum[b] = s[255];
}

__global__ void k_scan2() {
    __shared__ int s[256];
    int t = threadIdx.x;
    int v = (t < NB) ? g_bsum[t] : 0;
    s[t] = v; __syncthreads();
#pragma unroll
    for (int off = 1; off < 256; off <<= 1) {
        int x = 0;
        if (t >= off) x = s[t - off];
        __syncthreads();
        if (t >= off) s[t] += x;
        __syncthreads();
    }
    g_boff[t] = s[t] - v;               // exclusive block offsets
}

__global__ void k_scan3() {
    int i = blockIdx.x * blockDim.x + threadIdx.x;
    if (i >= NN) return;
    int start = g_tmp[i] - g_degi[i] + g_boff[i >> 8];
    g_start[i] = start;
    g_cur[i] = start;
}

__global__ void k_fill(const void* __restrict__ edge) {
    int i = blockIdx.x * blockDim.x + threadIdx.x;
    if (i >= NE) return;
    int s = edge_at(edge, i);
    int d = edge_at(edge, (long long)NE + i);
    int pos = atomicAdd(&g_cur[d], 1);
    g_csrc[pos] = s;
    g_cw[pos] = g_dinv[s] * g_dinv[d];
}

// ---------------- SGEMM: g_T[M,128] = (relu?)A[M,128] @ W[128,128] ----------------
template<bool RELU_IN, int SRC>
__global__ void __launch_bounds__(256) k_gemm(const float* __restrict__ Aext,
                                              const float* __restrict__ W) {
    const float* A = (SRC == 0) ? Aext : (SRC == 1 ? (const float*)g_H0 : (const float*)g_H1);

    __shared__ float As[8][128];
    __shared__ float Bs[8][128];
    const int tid = threadIdx.x;          // 256 threads
    const int blockRow = blockIdx.x * 128;
    const int ty = tid >> 4;              // 0..15
    const int tx = tid & 15;              // 0..15

    const int a_r = tid >> 1;             // 0..127
    const int a_c = (tid & 1) * 4;        // 0 or 4
    const int b_r = tid >> 5;             // 0..7
    const int b_c = (tid & 31) * 4;       // 0..124

    float acc[8][8];
#pragma unroll
    for (int i = 0; i < 8; i++)
#pragma unroll
        for (int j = 0; j < 8; j++) acc[i][j] = 0.f;

    for (int k0 = 0; k0 < 128; k0 += 8) {
        float4 av = make_float4(0.f, 0.f, 0.f, 0.f);
        int gr = blockRow + a_r;
        if (gr < NN) av = *(const float4*)(A + (size_t)gr * 128 + k0 + a_c);
        if (RELU_IN) {
            av.x = fmaxf(av.x, 0.f); av.y = fmaxf(av.y, 0.f);
            av.z = fmaxf(av.z, 0.f); av.w = fmaxf(av.w, 0.f);
        }
        As[a_c + 0][a_r] = av.x;
        As[a_c + 1][a_r] = av.y;
        As[a_c + 2][a_r] = av.z;
        As[a_c + 3][a_r] = av.w;

        *(float4*)&Bs[b_r][b_c] = *(const float4*)(W + (size_t)(k0 + b_r) * 128 + b_c);
        __syncthreads();

#pragma unroll
        for (int k = 0; k < 8; k++) {
            float4 ra0 = *(const float4*)&As[k][ty * 8];
            float4 ra1 = *(const float4*)&As[k][ty * 8 + 4];
            float4 rb0 = *(const float4*)&Bs[k][tx * 8];
            float4 rb1 = *(const float4*)&Bs[k][tx * 8 + 4];
            float ra[8] = {ra0.x, ra0.y, ra0.z, ra0.w, ra1.x, ra1.y, ra1.z, ra1.w};
            float rb[8] = {rb0.x, rb0.y, rb0.z, rb0.w, rb1.x, rb1.y, rb1.z, rb1.w};
#pragma unroll
            for (int i = 0; i < 8; i++)
#pragma unroll
                for (int j = 0; j < 8; j++) acc[i][j] = fmaf(ra[i], rb[j], acc[i][j]);
        }
        __syncthreads();
    }

#pragma unroll
    for (int i = 0; i < 8; i++) {
        int r = blockRow + ty * 8 + i;
        if (r >= NN) continue;
#pragma unroll
        for (int j = 0; j < 8; j++) {
            g_T[(size_t)r * 128 + tx * 8 + j] = acc[i][j];
        }
    }
}

// ---------------- gather: O[d] = T[d]*dinv[d]^2 + b + sum_e T[src_e]*w_e ----------------
// One warp per dst node; register accumulation; single store; NO float atomics.
template<int DST>
__global__ void __launch_bounds__(256) k_gather(const float* __restrict__ b) {
    float* O = (DST == 1) ? g_H0 : g_H1;
    int node = (blockIdx.x * blockDim.x + threadIdx.x) >> 5;
    int lane = threadIdx.x & 31;
    if (node >= NN) return;
    int c = lane * 4;

    float dv = g_dinv[node];
    float d2 = dv * dv;
    float4 bb = *(const float4*)(b + c);
    float4 t0 = *(const float4*)(g_T + (size_t)node * 128 + c);
    float4 acc;
    acc.x = fmaf(t0.x, d2, bb.x);
    acc.y = fmaf(t0.y, d2, bb.y);
    acc.z = fmaf(t0.z, d2, bb.z);
    acc.w = fmaf(t0.w, d2, bb.w);

    int beg = g_start[node];
    int end = beg + g_degi[node];
    for (int e = beg; e < end; e++) {
        int s = g_csrc[e];
        float w = g_cw[e];
        float4 v = *(const float4*)(g_T + (size_t)s * 128 + c);
        acc.x = fmaf(v.x, w, acc.x);
        acc.y = fmaf(v.y, w, acc.y);
        acc.z = fmaf(v.z, w, acc.z);
        acc.w = fmaf(v.w, w, acc.w);
    }
    *(float4*)(O + (size_t)node * 128 + c) = acc;
}

// ---------------- pooling: sums[batch[i]] += relu(H0[i]) ----------------
__global__ void __launch_bounds__(256) k_pool(const void* __restrict__ batch) {
    int node = (blockIdx.x * blockDim.x + threadIdx.x) >> 5;
    int lane = threadIdx.x & 31;
    if (node >= NN) return;
    int g = batch_at(batch, node);
    float4 v = *(const float4*)(g_H0 + (size_t)node * 128 + lane * 4);
    float* p = g_sums + g * 128 + lane * 4;
    atomicAdd(p + 0, fmaxf(v.x, 0.f));
    atomicAdd(p + 1, fmaxf(v.y, 0.f));
    atomicAdd(p + 2, fmaxf(v.z, 0.f));
    atomicAdd(p + 3, fmaxf(v.w, 0.f));
    if (lane == 0) atomicAdd(&g_cnt[g], 1);
}

// ---------------- head: out[g] = relu(mean @ Wf1 + bf1) @ Wf2 + bf2 ----------------
__global__ void __launch_bounds__(64) k_head(const float* __restrict__ Wf1,
                                             const float* __restrict__ bf1,
                                             const float* __restrict__ Wf2,
                                             const float* __restrict__ bf2,
                                             float* __restrict__ out) {
    int g = blockIdx.x;
    int j = threadIdx.x;          // 0..63
    __shared__ float hg[128];
    __shared__ float red[2];
    float invc = 1.f / fmaxf((float)g_cnt[g], 1.f);
    for (int k = j; k < 128; k += 64) hg[k] = g_sums[g * 128 + k] * invc;
    __syncthreads();
    float acc = bf1[j];
#pragma unroll
    for (int k = 0; k < 128; k++) acc = fmaf(hg[k], Wf1[k * 64 + j], acc);
    acc = fmaxf(acc, 0.f) * Wf2[j];
#pragma unroll
    for (int off = 16; off; off >>= 1) acc += __shfl_down_sync(0xffffffffu, acc, off);
    if ((j & 31) == 0) red[j >> 5] = acc;
    __syncthreads();
    if (j == 0) out[g] = red[0] + red[1] + bf2[0];
}

// ---------------- launch ----------------
extern "C" void kernel_launch(void* const* d_in, const int* in_sizes, int n_in,
                              void* d_out, int out_size) {
    const float* x    = (const float*)d_in[0];
    const void*  edge = d_in[1];
    const void*  bat  = d_in[2];
    const float* W1 = (const float*)d_in[3];
    const float* b1 = (const float*)d_in[4];
    const float* W2 = (const float*)d_in[5];
    const float* b2 = (const float*)d_in[6];
    const float* W3 = (const float*)d_in[7];
    const float* b3 = (const float*)d_in[8];
    const float* Wf1 = (const float*)d_in[9];
    const float* bf1 = (const float*)d_in[10];
    const float* Wf2 = (const float*)d_in[11];
    const float* bf2 = (const float*)d_in[12];
    float* out = (float*)d_out;

    const int TPB = 256;
    k_detect<<<1, 32>>>(edge, bat);
    k_zero<<<(NG * F + TPB - 1) / TPB, TPB>>>();
    k_deg <<<(NE + TPB - 1) / TPB, TPB>>>(edge);
    k_dinv<<<(NN + TPB - 1) / TPB, TPB>>>();
    k_scan1<<<NB, 256>>>();
    k_scan2<<<1, 256>>>();
    k_scan3<<<NB, 256>>>();
    k_fill<<<(NE + TPB - 1) / TPB, TPB>>>(edge);

    const int gemmGrid = (NN + 127) / 128;
    const int gathGrid = (int)(((long long)NN * 32 + TPB - 1) / TPB);

    // layer 1: x -> H0
    k_gemm<false, 0><<<gemmGrid, 256>>>(x, W1);
    k_gather<1><<<gathGrid, TPB>>>(b1);
    // layer 2: H0 -> H1
    k_gemm<true, 1><<<gemmGrid, 256>>>(nullptr, W2);
    k_gather<2><<<gathGrid, TPB>>>(b2);
    // layer 3: H1 -> H0
    k_gemm<true, 2><<<gemmGrid, 256>>>(nullptr, W3);
    k_gather<1><<<gathGrid, TPB>>>(b3);

    // pool + head
    k_pool<<<(int)(((long long)NN * 32 + TPB - 1) / TPB), TPB>>>(bat);
    k_head<<<NG, 64>>>(Wf1, bf1, Wf2, bf2, out);
}

// round 12
// speedup vs baseline: 2.5222x; 1.0802x over previous
#include <cuda_runtime.h>
#include <cuda_bf16.h>
#include <cstdint>

#define NN 50000
#define NE 600000
#define NG 500
#define F  128
#define NB 196   // (NN+255)/256

// ---------------- scratch (static __device__, no allocation) ----------------
__device__ __align__(16) float g_T [NN * F];   // t = h_in @ W (raw)
__device__ __align__(16) float g_H0[NN * F];   // layer outputs (ping)
__device__ __align__(16) float g_H1[NN * F];   // layer outputs (pong)
__device__ int   g_degi[NN];
__device__ float g_dinv[NN];
__device__ int   g_tmp [NN];
__device__ int   g_bsum[256];
__device__ int   g_boff[256];
__device__ int   g_start[NN];
__device__ int   g_cur [NN];
__device__ int   g_csrc[NE];
__device__ float g_cw  [NE];
__device__ __align__(16) float g_sums[NG * F];
__device__ int   g_cnt [NG];
__device__ int   g_e64;   // 1 if edge_index is int64, 0 if int32
__device__ int   g_b64;   // 1 if batch is int64, 0 if int32

// ---------------- dtype detection (int64 vs silently-downcast int32) ----------------
__global__ void k_detect(const void* edge, const void* batch) {
    if (threadIdx.x != 0 || blockIdx.x != 0) return;
    const long long* e64 = (const long long*)edge;
    int ok = 1;
    for (int i = 0; i < 256; i++) {
        long long v = e64[i];
        if (v < 0 || v >= NN) { ok = 0; break; }
    }
    g_e64 = ok;
    const long long* b64 = (const long long*)batch;
    ok = 1;
    for (int i = 0; i < 256; i++) {
        long long v = b64[i];
        if (v < 0 || v >= NG) { ok = 0; break; }
    }
    g_b64 = ok;
}

__device__ __forceinline__ int edge_at(const void* edge, long long idx) {
    return g_e64 ? (int)((const long long*)edge)[idx] : ((const int*)edge)[idx];
}
__device__ __forceinline__ int batch_at(const void* batch, int idx) {
    return g_b64 ? (int)((const long long*)batch)[idx] : ((const int*)batch)[idx];
}

// ---------------- prep ----------------
__global__ void k_zero() {
    int i = blockIdx.x * blockDim.x + threadIdx.x;
    if (i < NN) g_degi[i] = 0;
    if (i < NG * F) g_sums[i] = 0.f;
    if (i < NG) g_cnt[i] = 0;
}

__global__ void k_deg(const void* __restrict__ edge) {
    int i = blockIdx.x * blockDim.x + threadIdx.x;
    if (i >= NE) return;
    int d = edge_at(edge, (long long)NE + i);
    atomicAdd(&g_degi[d], 1);
}

__global__ void k_dinv() {
    int i = blockIdx.x * blockDim.x + threadIdx.x;
    if (i >= NN) return;
    g_dinv[i] = rsqrtf((float)(g_degi[i] + 1));   // +1 self loop
}

// ---- 3-kernel exclusive prefix sum over g_degi -> g_start ----
__global__ void k_scan1() {
    __shared__ int s[256];
    int b = blockIdx.x, t = threadIdx.x;
    int i = b * 256 + t;
    int v = (i < NN) ? g_degi[i] : 0;
    s[t] = v; __syncthreads();
#pragma unroll
    for (int off = 1; off < 256; off <<= 1) {
        int x = 0;
        if (t >= off) x = s[t - off];
        __syncthreads();
        if (t >= off) s[t] += x;
        __syncthreads();
    }
    if (i < NN) g_tmp[i] = s[t];        // inclusive within block
    if (t == 255) g_bsum[b] = s[255];
}

__global__ void k_scan2() {
    __shared__ int s[256];
    int t = threadIdx.x;
    int v = (t < NB) ? g_bsum[t] : 0;
    s[t] = v; __syncthreads();
#pragma unroll
    for (int off = 1; off < 256; off <<= 1) {
        int x = 0;
        if (t >= off) x = s[t - off];
        __syncthreads();
        if (t >= off) s[t] += x;
        __syncthreads();
    }
    g_boff[t] = s[t] - v;               // exclusive block offsets
}

__global__ void k_scan3() {
    int i = blockIdx.x * blockDim.x + threadIdx.x;
    if (i >= NN) return;
    int start = g_tmp[i] - g_degi[i] + g_boff[i >> 8];
    g_start[i] = start;
    g_cur[i] = start;
}

__global__ void k_fill(const void* __restrict__ edge) {
    int i = blockIdx.x * blockDim.x + threadIdx.x;
    if (i >= NE) return;
    int s = edge_at(edge, i);
    int d = edge_at(edge, (long long)NE + i);
    int pos = atomicAdd(&g_cur[d], 1);
    g_csrc[pos] = s;
    g_cw[pos] = g_dinv[s] * g_dinv[d];
}

// ---------------- tf32 helpers ----------------
__device__ __forceinline__ uint32_t f2tf(float f) {
    uint32_t u;
    asm("cvt.rna.tf32.f32 %0, %1;" : "=r"(u) : "f"(f));
    return u;
}

__device__ __forceinline__ void mma8(float* d, const uint32_t* a, uint32_t b0, uint32_t b1) {
    asm volatile(
        "mma.sync.aligned.m16n8k8.row.col.f32.tf32.tf32.f32 "
        "{%0,%1,%2,%3},{%4,%5,%6,%7},{%8,%9},{%0,%1,%2,%3};"
        : "+f"(d[0]), "+f"(d[1]), "+f"(d[2]), "+f"(d[3])
        : "r"(a[0]), "r"(a[1]), "r"(a[2]), "r"(a[3]), "r"(b0), "r"(b1));
}

// ---------------- tensor-core GEMM: g_T[M,128] = (relu?)A[M,128] @ W[128,128] ----------------
// 3xTF32 precision scheme. 512 threads = 16 warps (8 m-bands of 32 x 2 n-halves of 64).
// W pre-converted to fragment-ordered tf32 hi/lo in dynamic smem (once per block).
template<bool RELU_IN, int SRC>
__global__ void __launch_bounds__(512) k_gemm_tc(const float* __restrict__ Aext,
                                                 const float* __restrict__ W) {
    extern __shared__ uint32_t sb[];      // Bh[16384], Bl[16384]
    uint32_t* Bh = sb;
    uint32_t* Bl = sb + 16384;
    const float* A = (SRC == 0) ? Aext : (SRC == 1 ? (const float*)g_H0 : (const float*)g_H1);
    const int tid = threadIdx.x;

    // Build B fragments: element e = ((NT*16 + KS)*32 + lane)*2 + j
    //   holds W[KS*8 + (lane&3) + 4*j][NT*8 + (lane>>2)]
    for (int e = tid; e < 16384; e += 512) {
        int j  = e & 1;
        int l  = (e >> 1) & 31;
        int KS = (e >> 6) & 15;
        int NT = e >> 10;
        int k = KS * 8 + (l & 3) + 4 * j;
        int n = NT * 8 + (l >> 2);
        float v = W[k * 128 + n];
        uint32_t hi = f2tf(v);
        float lo = v - __uint_as_float(hi);
        Bh[e] = hi;
        Bl[e] = f2tf(lo);
    }
    __syncthreads();

    const int wid = tid >> 5, lane = tid & 31;
    const int g = lane >> 2, t4 = lane & 3;
    const int warp_m = wid >> 1, warp_n = wid & 1;
    const int m_base = blockIdx.x * 256 + warp_m * 32;
    const int NTb = warp_n * 8;

    // 4 fragment rows for this thread: m_base + {0,8,16,24} + g
    int rr[4];
    const float* Ap[4];
    bool vr[4];
#pragma unroll
    for (int q = 0; q < 4; q++) {
        rr[q] = m_base + q * 8 + g;
        vr[q] = rr[q] < NN;
        Ap[q] = A + (size_t)rr[q] * 128;
    }

    float acc[2][8][4];
#pragma unroll
    for (int mt = 0; mt < 2; mt++)
#pragma unroll
        for (int nt = 0; nt < 8; nt++)
#pragma unroll
            for (int q = 0; q < 4; q++) acc[mt][nt][q] = 0.f;

#pragma unroll
    for (int ks = 0; ks < 16; ks++) {
        const int k0 = ks * 8 + t4;
        // A fragments: mt in {0,1}; rows: mt*16 + {0,8}; cols k0, k0+4
        float af[2][4];
#pragma unroll
        for (int mt = 0; mt < 2; mt++) {
            af[mt][0] = vr[mt * 2 + 0] ? Ap[mt * 2 + 0][k0]     : 0.f;
            af[mt][1] = vr[mt * 2 + 1] ? Ap[mt * 2 + 1][k0]     : 0.f;
            af[mt][2] = vr[mt * 2 + 0] ? Ap[mt * 2 + 0][k0 + 4] : 0.f;
            af[mt][3] = vr[mt * 2 + 1] ? Ap[mt * 2 + 1][k0 + 4] : 0.f;
        }
        uint32_t ah[2][4], al[2][4];
#pragma unroll
        for (int mt = 0; mt < 2; mt++)
#pragma unroll
            for (int q = 0; q < 4; q++) {
                float v = af[mt][q];
                if (RELU_IN) v = fmaxf(v, 0.f);
                uint32_t hi = f2tf(v);
                ah[mt][q] = hi;
                al[mt][q] = f2tf(v - __uint_as_float(hi));
            }

#pragma unroll
        for (int nt = 0; nt < 8; nt++) {
            int base = (((NTb + nt) * 16 + ks) * 32 + lane) * 2;
            uint32_t bh0 = Bh[base], bh1 = Bh[base + 1];
            uint32_t bl0 = Bl[base], bl1 = Bl[base + 1];
#pragma unroll
            for (int mt = 0; mt < 2; mt++) {
                mma8(acc[mt][nt], ah[mt], bh0, bh1);
                mma8(acc[mt][nt], al[mt], bh0, bh1);
                mma8(acc[mt][nt], ah[mt], bl0, bl1);
            }
        }
    }

    // Epilogue: c0:(rg, n0+2*t4) c1:(rg, +1) c2:(rg+8, ..) c3
#pragma unroll
    for (int mt = 0; mt < 2; mt++) {
        int r_lo = m_base + mt * 16 + g;
        int r_hi = r_lo + 8;
#pragma unroll
        for (int nt = 0; nt < 8; nt++) {
            int col = (NTb + nt) * 8 + t4 * 2;
            if (r_lo < NN)
                *(float2*)(g_T + (size_t)r_lo * 128 + col) = make_float2(acc[mt][nt][0], acc[mt][nt][1]);
            if (r_hi < NN)
                *(float2*)(g_T + (size_t)r_hi * 128 + col) = make_float2(acc[mt][nt][2], acc[mt][nt][3]);
        }
    }
}

// ---------------- gather: O[d] = T[d]*dinv[d]^2 + b + sum_e T[src_e]*w_e ----------------
template<int DST>
__global__ void __launch_bounds__(256) k_gather(const float* __restrict__ b) {
    float* O = (DST == 1) ? g_H0 : g_H1;
    int node = (blockIdx.x * blockDim.x + threadIdx.x) >> 5;
    int lane = threadIdx.x & 31;
    if (node >= NN) return;
    int c = lane * 4;

    float dv = g_dinv[node];
    float d2 = dv * dv;
    float4 bb = *(const float4*)(b + c);
    float4 t0 = *(const float4*)(g_T + (size_t)node * 128 + c);
    float4 acc;
    acc.x = fmaf(t0.x, d2, bb.x);
    acc.y = fmaf(t0.y, d2, bb.y);
    acc.z = fmaf(t0.z, d2, bb.z);
    acc.w = fmaf(t0.w, d2, bb.w);

    int beg = g_start[node];
    int end = beg + g_degi[node];
    for (int e = beg; e < end; e++) {
        int s = g_csrc[e];
        float w = g_cw[e];
        float4 v = *(const float4*)(g_T + (size_t)s * 128 + c);
        acc.x = fmaf(v.x, w, acc.x);
        acc.y = fmaf(v.y, w, acc.y);
        acc.z = fmaf(v.z, w, acc.z);
        acc.w = fmaf(v.w, w, acc.w);
    }
    *(float4*)(O + (size_t)node * 128 + c) = acc;
}

// ---------------- pooling: sums[batch[i]] += relu(H0[i]) ----------------
__global__ void __launch_bounds__(256) k_pool(const void* __restrict__ batch) {
    int node = (blockIdx.x * blockDim.x + threadIdx.x) >> 5;
    int lane = threadIdx.x & 31;
    if (node >= NN) return;
    int g = batch_at(batch, node);
    float4 v = *(const float4*)(g_H0 + (size_t)node * 128 + lane * 4);
    float* p = g_sums + g * 128 + lane * 4;
    atomicAdd(p + 0, fmaxf(v.x, 0.f));
    atomicAdd(p + 1, fmaxf(v.y, 0.f));
    atomicAdd(p + 2, fmaxf(v.z, 0.f));
    atomicAdd(p + 3, fmaxf(v.w, 0.f));
    if (lane == 0) atomicAdd(&g_cnt[g], 1);
}

// ---------------- head: out[g] = relu(mean @ Wf1 + bf1) @ Wf2 + bf2 ----------------
__global__ void __launch_bounds__(64) k_head(const float* __restrict__ Wf1,
                                             const float* __restrict__ bf1,
                                             const float* __restrict__ Wf2,
                                             const float* __restrict__ bf2,
                                             float* __restrict__ out) {
    int g = blockIdx.x;
    int j = threadIdx.x;          // 0..63
    __shared__ float hg[128];
    __shared__ float red[2];
    float invc = 1.f / fmaxf((float)g_cnt[g], 1.f);
    for (int k = j; k < 128; k += 64) hg[k] = g_sums[g * 128 + k] * invc;
    __syncthreads();
    float acc = bf1[j];
#pragma unroll
    for (int k = 0; k < 128; k++) acc = fmaf(hg[k], Wf1[k * 64 + j], acc);
    acc = fmaxf(acc, 0.f) * Wf2[j];
#pragma unroll
    for (int off = 16; off; off >>= 1) acc += __shfl_down_sync(0xffffffffu, acc, off);
    if ((j & 31) == 0) red[j >> 5] = acc;
    __syncthreads();
    if (j == 0) out[g] = red[0] + red[1] + bf2[0];
}

// ---------------- launch ----------------
extern "C" void kernel_launch(void* const* d_in, const int* in_sizes, int n_in,
                              void* d_out, int out_size) {
    const float* x    = (const float*)d_in[0];
    const void*  edge = d_in[1];
    const void*  bat  = d_in[2];
    const float* W1 = (const float*)d_in[3];
    const float* b1 = (const float*)d_in[4];
    const float* W2 = (const float*)d_in[5];
    const float* b2 = (const float*)d_in[6];
    const float* W3 = (const float*)d_in[7];
    const float* b3 = (const float*)d_in[8];
    const float* Wf1 = (const float*)d_in[9];
    const float* bf1 = (const float*)d_in[10];
    const float* Wf2 = (const float*)d_in[11];
    const float* bf2 = (const float*)d_in[12];
    float* out = (float*)d_out;

    const int SMEM = 131072;   // Bh + Bl fragment arrays
    cudaFuncSetAttribute(k_gemm_tc<false, 0>, cudaFuncAttributeMaxDynamicSharedMemorySize, SMEM);
    cudaFuncSetAttribute(k_gemm_tc<true, 1>,  cudaFuncAttributeMaxDynamicSharedMemorySize, SMEM);
    cudaFuncSetAttribute(k_gemm_tc<true, 2>,  cudaFuncAttributeMaxDynamicSharedMemorySize, SMEM);

    const int TPB = 256;
    k_detect<<<1, 32>>>(edge, bat);
    k_zero<<<(NG * F + TPB - 1) / TPB, TPB>>>();
    k_deg <<<(NE + TPB - 1) / TPB, TPB>>>(edge);
    k_dinv<<<(NN + TPB - 1) / TPB, TPB>>>();
    k_scan1<<<NB, 256>>>();
    k_scan2<<<1, 256>>>();
    k_scan3<<<NB, 256>>>();
    k_fill<<<(NE + TPB - 1) / TPB, TPB>>>(edge);

    const int gemmGrid = (NN + 255) / 256;   // 196
    const int gathGrid = (int)(((long long)NN * 32 + TPB - 1) / TPB);

    // layer 1: x -> H0
    k_gemm_tc<false, 0><<<gemmGrid, 512, SMEM>>>(x, W1);
    k_gather<1><<<gathGrid, TPB>>>(b1);
    // layer 2: H0 -> H1
    k_gemm_tc<true, 1><<<gemmGrid, 512, SMEM>>>(nullptr, W2);
    k_gather<2><<<gathGrid, TPB>>>(b2);
    // layer 3: H1 -> H0
    k_gemm_tc<true, 2><<<gemmGrid, 512, SMEM>>>(nullptr, W3);
    k_gather<1><<<gathGrid, TPB>>>(b3);

    // pool + head
    k_pool<<<(int)(((long long)NN * 32 + TPB - 1) / TPB), TPB>>>(bat);
    k_head<<<NG, 64>>>(Wf1, bf1, Wf2, bf2, out);
}

// round 13
// speedup vs baseline: 3.1183x; 1.2363x over previous
#include <cuda_runtime.h>
#include <cuda_bf16.h>
#include <cstdint>

#define NN 50000
#define NE 600000
#define NG 500
#define F  128
#define NB 196   // (NN+255)/256

// ---------------- scratch (static __device__, no allocation) ----------------
__device__ __align__(16) float g_T [NN * F];   // t = h_in @ W (raw)
__device__ __align__(16) float g_H0[NN * F];   // layer outputs (ping)
__device__ __align__(16) float g_H1[NN * F];   // layer outputs (pong)
__device__ int   g_degi[NN];
__device__ float g_dinv[NN];
__device__ int   g_tmp [NN];
__device__ int   g_bsum[256];
__device__ int   g_boff[256];
__device__ int   g_start[NN];
__device__ int   g_cur [NN];
__device__ int   g_csrc[NE];
__device__ float g_cw  [NE];
__device__ __align__(16) float g_sums[NG * F];
__device__ int   g_cnt [NG];
__device__ int   g_e64;
__device__ int   g_b64;
__device__ __align__(16) uint32_t g_Bh[3 * 16384];   // tf32 hi fragments, 3 layers
__device__ __align__(16) uint32_t g_Bl[3 * 16384];   // tf32 lo fragments

// ---------------- dtype detection (parallel; int64 vs silently-downcast int32) ----------------
__global__ void k_detect(const void* edge, const void* batch) {
    __shared__ int bad[2];
    int t = threadIdx.x;
    if (t < 2) bad[t] = 0;
    __syncthreads();
    if (t < 256) {
        long long v = ((const long long*)edge)[t];
        if (v < 0 || v >= NN) bad[0] = 1;
    } else {
        long long v = ((const long long*)batch)[t - 256];
        if (v < 0 || v >= NG) bad[1] = 1;
    }
    __syncthreads();
    if (t == 0) { g_e64 = !bad[0]; g_b64 = !bad[1]; }
}

__device__ __forceinline__ int edge_at(const void* edge, long long idx) {
    return g_e64 ? (int)((const long long*)edge)[idx] : ((const int*)edge)[idx];
}
__device__ __forceinline__ int batch_at(const void* batch, int idx) {
    return g_b64 ? (int)((const long long*)batch)[idx] : ((const int*)batch)[idx];
}

// ---------------- prep ----------------
__global__ void k_zero() {
    int i = blockIdx.x * blockDim.x + threadIdx.x;
    if (i < NN) g_degi[i] = 0;
    if (i < NG * F) g_sums[i] = 0.f;
    if (i < NG) g_cnt[i] = 0;
}

__global__ void k_deg(const void* __restrict__ edge) {
    int i = blockIdx.x * blockDim.x + threadIdx.x;
    if (i >= NE) return;
    int d = edge_at(edge, (long long)NE + i);
    atomicAdd(&g_degi[d], 1);
}

// ---- 3-kernel exclusive prefix sum over g_degi -> g_start (+dinv fold) ----
__global__ void k_scan1() {
    __shared__ int s[256];
    int b = blockIdx.x, t = threadIdx.x;
    int i = b * 256 + t;
    int v = (i < NN) ? g_degi[i] : 0;
    s[t] = v; __syncthreads();
#pragma unroll
    for (int off = 1; off < 256; off <<= 1) {
        int x = 0;
        if (t >= off) x = s[t - off];
        __syncthreads();
        if (t >= off) s[t] += x;
        __syncthreads();
    }
    if (i < NN) g_tmp[i] = s[t];
    if (t == 255) g_bsum[b] = s[255];
}

__global__ void k_scan2() {
    __shared__ int s[256];
    int t = threadIdx.x;
    int v = (t < NB) ? g_bsum[t] : 0;
    s[t] = v; __syncthreads();
#pragma unroll
    for (int off = 1; off < 256; off <<= 1) {
        int x = 0;
        if (t >= off) x = s[t - off];
        __syncthreads();
        if (t >= off) s[t] += x;
        __syncthreads();
    }
    g_boff[t] = s[t] - v;
}

__global__ void k_scan3() {
    int i = blockIdx.x * blockDim.x + threadIdx.x;
    if (i >= NN) return;
    int deg = g_degi[i];
    int start = g_tmp[i] - deg + g_boff[i >> 8];
    g_start[i] = start;
    g_cur[i] = start;
    g_dinv[i] = rsqrtf((float)(deg + 1));   // +1 self loop
}

__global__ void k_fill(const void* __restrict__ edge) {
    int i = blockIdx.x * blockDim.x + threadIdx.x;
    if (i >= NE) return;
    int s = edge_at(edge, i);
    int d = edge_at(edge, (long long)NE + i);
    int pos = atomicAdd(&g_cur[d], 1);
    g_csrc[pos] = s;
    g_cw[pos] = g_dinv[s] * g_dinv[d];
}

// ---------------- tf32 helpers ----------------
__device__ __forceinline__ uint32_t f2tf(float f) {
    uint32_t u;
    asm("cvt.rna.tf32.f32 %0, %1;" : "=r"(u) : "f"(f));
    return u;
}

__device__ __forceinline__ void mma8(float* d, const uint32_t* a, uint32_t b0, uint32_t b1) {
    asm volatile(
        "mma.sync.aligned.m16n8k8.row.col.f32.tf32.tf32.f32 "
        "{%0,%1,%2,%3},{%4,%5,%6,%7},{%8,%9},{%0,%1,%2,%3};"
        : "+f"(d[0]), "+f"(d[1]), "+f"(d[2]), "+f"(d[3])
        : "r"(a[0]), "r"(a[1]), "r"(a[2]), "r"(a[3]), "r"(b0), "r"(b1));
}

// ---------------- one-time W -> tf32 hi/lo fragment conversion (all 3 layers) ----------------
// fragment e = ((NT*16 + KS)*32 + lane)*2 + j  holds  W[KS*8 + (lane&3) + 4*j][NT*8 + (lane>>2)]
__global__ void k_wconv(const float* __restrict__ W1,
                        const float* __restrict__ W2,
                        const float* __restrict__ W3) {
    int e = blockIdx.x * blockDim.x + threadIdx.x;
    if (e >= 3 * 16384) return;
    int l = e >> 14;
    int f = e & 16383;
    const float* W = (l == 0) ? W1 : (l == 1 ? W2 : W3);
    int j  = f & 1;
    int ln = (f >> 1) & 31;
    int KS = (f >> 6) & 15;
    int NT = f >> 10;
    int k = KS * 8 + (ln & 3) + 4 * j;
    int n = NT * 8 + (ln >> 2);
    float v = W[k * 128 + n];
    uint32_t hi = f2tf(v);
    g_Bh[e] = hi;
    g_Bl[e] = f2tf(v - __uint_as_float(hi));
}

// ---------------- tensor-core GEMM: g_T[M,128] = (relu?)A[M,128] @ W[128,128] ----------------
// 3xTF32. Block = 512 thr = 16 warps, each warp one m16 band; BM=256, BN=64 (nhalf per block).
// B fragments copied from prebuilt global arrays (64KB smem -> 2 blocks/SM).
template<bool RELU_IN, int SRC, int L>
__global__ void __launch_bounds__(512, 2) k_gemm_tc(const float* __restrict__ Aext) {
    extern __shared__ uint32_t sb[];      // sBh[8192], sBl[8192]
    uint32_t* sBh = sb;
    uint32_t* sBl = sb + 8192;
    const float* A = (SRC == 0) ? Aext : (SRC == 1 ? (const float*)g_H0 : (const float*)g_H1);
    const int tid = threadIdx.x;
    const int nhalf = blockIdx.x & 1;
    const int mblk  = blockIdx.x >> 1;

    {
        const uint4* srcH = (const uint4*)(g_Bh + L * 16384 + nhalf * 8192);
        const uint4* srcL = (const uint4*)(g_Bl + L * 16384 + nhalf * 8192);
        uint4* dH = (uint4*)sBh;
        uint4* dL = (uint4*)sBl;
        for (int i = tid; i < 2048; i += 512) { dH[i] = srcH[i]; dL[i] = srcL[i]; }
    }
    __syncthreads();

    const int wid = tid >> 5, lane = tid & 31;
    const int g = lane >> 2, t4 = lane & 3;
    const int m_base = mblk * 256 + wid * 16;
    const int r0 = m_base + g, r1 = r0 + 8;
    const bool v0 = r0 < NN, v1 = r1 < NN;
    const float* A0 = A + (size_t)r0 * 128;
    const float* A1 = A + (size_t)r1 * 128;

    float acc[8][4];
#pragma unroll
    for (int nt = 0; nt < 8; nt++)
#pragma unroll
        for (int q = 0; q < 4; q++) acc[nt][q] = 0.f;

#pragma unroll
    for (int ks = 0; ks < 16; ks++) {
        const int k0 = ks * 8 + t4;
        float f0 = v0 ? A0[k0]     : 0.f;
        float f1 = v1 ? A1[k0]     : 0.f;
        float f2 = v0 ? A0[k0 + 4] : 0.f;
        float f3 = v1 ? A1[k0 + 4] : 0.f;
        if (RELU_IN) {
            f0 = fmaxf(f0, 0.f); f1 = fmaxf(f1, 0.f);
            f2 = fmaxf(f2, 0.f); f3 = fmaxf(f3, 0.f);
        }
        uint32_t ah[4], al[4];
        float fv[4] = {f0, f1, f2, f3};
#pragma unroll
        for (int q = 0; q < 4; q++) {
            uint32_t hi = f2tf(fv[q]);
            ah[q] = hi;
            al[q] = f2tf(fv[q] - __uint_as_float(hi));
        }

#pragma unroll
        for (int nt = 0; nt < 8; nt++) {
            int base = ((nt * 16 + ks) * 32 + lane) * 2;
            uint32_t bh0 = sBh[base], bh1 = sBh[base + 1];
            uint32_t bl0 = sBl[base], bl1 = sBl[base + 1];
            mma8(acc[nt], ah, bh0, bh1);
            mma8(acc[nt], al, bh0, bh1);
            mma8(acc[nt], ah, bl0, bl1);
        }
    }

#pragma unroll
    for (int nt = 0; nt < 8; nt++) {
        int col = nhalf * 64 + nt * 8 + t4 * 2;
        if (v0) *(float2*)(g_T + (size_t)r0 * 128 + col) = make_float2(acc[nt][0], acc[nt][1]);
        if (v1) *(float2*)(g_T + (size_t)r1 * 128 + col) = make_float2(acc[nt][2], acc[nt][3]);
    }
}

// ---------------- gather: O[d] = T[d]*dinv[d]^2 + b + sum_e T[src_e]*w_e ----------------
// POOL variant (layer 3): skip H write, add relu(acc) straight into graph sums.
template<int DST, bool POOL>
__global__ void __launch_bounds__(256) k_gather(const float* __restrict__ b,
                                                const void* __restrict__ batch) {
    float* O = (DST == 1) ? g_H0 : g_H1;
    int node = (blockIdx.x * blockDim.x + threadIdx.x) >> 5;
    int lane = threadIdx.x & 31;
    if (node >= NN) return;
    int c = lane * 4;

    float dv = g_dinv[node];
    float d2 = dv * dv;
    float4 bb = *(const float4*)(b + c);
    float4 t0 = *(const float4*)(g_T + (size_t)node * 128 + c);
    float4 acc;
    acc.x = fmaf(t0.x, d2, bb.x);
    acc.y = fmaf(t0.y, d2, bb.y);
    acc.z = fmaf(t0.z, d2, bb.z);
    acc.w = fmaf(t0.w, d2, bb.w);

    int beg = g_start[node];
    int end = beg + g_degi[node];
    for (int e = beg; e < end; e++) {
        int s = g_csrc[e];
        float w = g_cw[e];
        float4 v = *(const float4*)(g_T + (size_t)s * 128 + c);
        acc.x = fmaf(v.x, w, acc.x);
        acc.y = fmaf(v.y, w, acc.y);
        acc.z = fmaf(v.z, w, acc.z);
        acc.w = fmaf(v.w, w, acc.w);
    }
    if (POOL) {
        int gph = batch_at(batch, node);
        float* p = g_sums + gph * 128 + c;
        atomicAdd(p + 0, fmaxf(acc.x, 0.f));
        atomicAdd(p + 1, fmaxf(acc.y, 0.f));
        atomicAdd(p + 2, fmaxf(acc.z, 0.f));
        atomicAdd(p + 3, fmaxf(acc.w, 0.f));
        if (lane == 0) atomicAdd(&g_cnt[gph], 1);
    } else {
        *(float4*)(O + (size_t)node * 128 + c) = acc;
    }
}

// ---------------- head: out[g] = relu(mean @ Wf1 + bf1) @ Wf2 + bf2 ----------------
__global__ void __launch_bounds__(64) k_head(const float* __restrict__ Wf1,
                                             const float* __restrict__ bf1,
                                             const float* __restrict__ Wf2,
                                             const float* __restrict__ bf2,
                                             float* __restrict__ out) {
    int g = blockIdx.x;
    int j = threadIdx.x;
    __shared__ float hg[128];
    __shared__ float red[2];
    float invc = 1.f / fmaxf((float)g_cnt[g], 1.f);
    for (int k = j; k < 128; k += 64) hg[k] = g_sums[g * 128 + k] * invc;
    __syncthreads();
    float acc = bf1[j];
#pragma unroll
    for (int k = 0; k < 128; k++) acc = fmaf(hg[k], Wf1[k * 64 + j], acc);
    acc = fmaxf(acc, 0.f) * Wf2[j];
#pragma unroll
    for (int off = 16; off; off >>= 1) acc += __shfl_down_sync(0xffffffffu, acc, off);
    if ((j & 31) == 0) red[j >> 5] = acc;
    __syncthreads();
    if (j == 0) out[g] = red[0] + red[1] + bf2[0];
}

// ---------------- launch ----------------
extern "C" void kernel_launch(void* const* d_in, const int* in_sizes, int n_in,
                              void* d_out, int out_size) {
    const float* x    = (const float*)d_in[0];
    const void*  edge = d_in[1];
    const void*  bat  = d_in[2];
    const float* W1 = (const float*)d_in[3];
    const float* b1 = (const float*)d_in[4];
    const float* W2 = (const float*)d_in[5];
    const float* b2 = (const float*)d_in[6];
    const float* W3 = (const float*)d_in[7];
    const float* b3 = (const float*)d_in[8];
    const float* Wf1 = (const float*)d_in[9];
    const float* bf1 = (const float*)d_in[10];
    const float* Wf2 = (const float*)d_in[11];
    const float* bf2 = (const float*)d_in[12];
    float* out = (float*)d_out;

    const int SMEM = 65536;   // sBh + sBl
    cudaFuncSetAttribute(k_gemm_tc<false, 0, 0>, cudaFuncAttributeMaxDynamicSharedMemorySize, SMEM);
    cudaFuncSetAttribute(k_gemm_tc<true, 1, 1>,  cudaFuncAttributeMaxDynamicSharedMemorySize, SMEM);
    cudaFuncSetAttribute(k_gemm_tc<true, 2, 2>,  cudaFuncAttributeMaxDynamicSharedMemorySize, SMEM);

    const int TPB = 256;
    k_detect<<<1, 512>>>(edge, bat);
    k_zero<<<(NG * F + TPB - 1) / TPB, TPB>>>();
    k_deg <<<(NE + TPB - 1) / TPB, TPB>>>(edge);
    k_scan1<<<NB, 256>>>();
    k_scan2<<<1, 256>>>();
    k_scan3<<<NB, 256>>>();
    k_fill<<<(NE + TPB - 1) / TPB, TPB>>>(edge);
    k_wconv<<<192, 256>>>(W1, W2, W3);

    const int gemmGrid = 2 * ((NN + 255) / 256);   // 392 (BN split)
    const int gathGrid = (int)(((long long)NN * 32 + TPB - 1) / TPB);

    // layer 1: x -> H0
    k_gemm_tc<false, 0, 0><<<gemmGrid, 512, SMEM>>>(x);
    k_gather<1, false><<<gathGrid, TPB>>>(b1, nullptr);
    // layer 2: H0 -> H1
    k_gemm_tc<true, 1, 1><<<gemmGrid, 512, SMEM>>>(nullptr);
    k_gather<2, false><<<gathGrid, TPB>>>(b2, nullptr);
    // layer 3: H1 -> (pool fused, no H write)
    k_gemm_tc<true, 2, 2><<<gemmGrid, 512, SMEM>>>(nullptr);
    k_gather<1, true><<<gathGrid, TPB>>>(b3, bat);

    k_head<<<NG, 64>>>(Wf1, bf1, Wf2, bf2, out);
}

// round 15
// speedup vs baseline: 3.3536x; 1.0755x over previous
#include <cuda_runtime.h>
#include <cuda_fp16.h>
#include <cstdint>

#define NN 50000
#define NE 600000
#define NG 500
#define F  128
#define NB 196   // (NN+255)/256

// ---------------- scratch (static __device__, no allocation) ----------------
__device__ __align__(16) __half g_T [NN * F];  // T' = (A@W)*dinv[row], fp16
__device__ __align__(16) float g_H0[NN * F];   // layer outputs (ping), post-relu
__device__ __align__(16) float g_H1[NN * F];   // layer outputs (pong), post-relu
__device__ int   g_degi[NN];
__device__ float g_dinv[NN];
__device__ int   g_tmp [NN];
__device__ int   g_bsum[256];
__device__ int   g_boff[256];
__device__ int   g_start[NN];
__device__ int   g_cur [NN];
__device__ int   g_csrc[NE];
__device__ __align__(16) float g_sums[NG * F];
__device__ int   g_cnt [NG];
__device__ int   g_e64;
__device__ int   g_b64;
__device__ __align__(16) uint32_t g_Bh[3 * 16384];   // tf32 hi fragments, 3 layers
__device__ __align__(16) uint32_t g_Bl[3 * 16384];   // tf32 lo fragments

// ---------------- dtype detection (parallel; int64 vs silently-downcast int32) ----------------
__global__ void k_detect(const void* edge, const void* batch) {
    __shared__ int bad[2];
    int t = threadIdx.x;
    if (t < 2) bad[t] = 0;
    __syncthreads();
    if (t < 256) {
        long long v = ((const long long*)edge)[t];
        if (v < 0 || v >= NN) bad[0] = 1;
    } else {
        long long v = ((const long long*)batch)[t - 256];
        if (v < 0 || v >= NG) bad[1] = 1;
    }
    __syncthreads();
    if (t == 0) { g_e64 = !bad[0]; g_b64 = !bad[1]; }
}

__device__ __forceinline__ int edge_at(const void* edge, long long idx) {
    return g_e64 ? (int)((const long long*)edge)[idx] : ((const int*)edge)[idx];
}
__device__ __forceinline__ int batch_at(const void* batch, int idx) {
    return g_b64 ? (int)((const long long*)batch)[idx] : ((const int*)batch)[idx];
}

// ---------------- prep ----------------
__global__ void k_zero() {
    int i = blockIdx.x * blockDim.x + threadIdx.x;
    if (i < NN) g_degi[i] = 0;
    if (i < NG * F) g_sums[i] = 0.f;
    if (i < NG) g_cnt[i] = 0;
}

__global__ void k_deg(const void* __restrict__ edge) {
    int i = blockIdx.x * blockDim.x + threadIdx.x;
    if (i >= NE) return;
    int d = edge_at(edge, (long long)NE + i);
    atomicAdd(&g_degi[d], 1);
}

// ---- 3-kernel exclusive prefix sum over g_degi -> g_start (+dinv fold) ----
__global__ void k_scan1() {
    __shared__ int s[256];
    int b = blockIdx.x, t = threadIdx.x;
    int i = b * 256 + t;
    int v = (i < NN) ? g_degi[i] : 0;
    s[t] = v; __syncthreads();
#pragma unroll
    for (int off = 1; off < 256; off <<= 1) {
        int x = 0;
        if (t >= off) x = s[t - off];
        __syncthreads();
        if (t >= off) s[t] += x;
        __syncthreads();
    }
    if (i < NN) g_tmp[i] = s[t];
    if (t == 255) g_bsum[b] = s[255];
}

__global__ void k_scan2() {
    __shared__ int s[256];
    int t = threadIdx.x;
    int v = (t < NB) ? g_bsum[t] : 0;
    s[t] = v; __syncthreads();
#pragma unroll
    for (int off = 1; off < 256; off <<= 1) {
        int x = 0;
        if (t >= off) x = s[t - off];
        __syncthreads();
        if (t >= off) s[t] += x;
        __syncthreads();
    }
    g_boff[t] = s[t] - v;
}

__global__ void k_scan3() {
    int i = blockIdx.x * blockDim.x + threadIdx.x;
    if (i >= NN) return;
    int deg = g_degi[i];
    int start = g_tmp[i] - deg + g_boff[i >> 8];
    g_start[i] = start;
    g_cur[i] = start;
    g_dinv[i] = rsqrtf((float)(deg + 1));   // +1 self loop
}

__global__ void k_fill(const void* __restrict__ edge) {
    int i = blockIdx.x * blockDim.x + threadIdx.x;
    if (i >= NE) return;
    int s = edge_at(edge, i);
    int d = edge_at(edge, (long long)NE + i);
    int pos = atomicAdd(&g_cur[d], 1);
    g_csrc[pos] = s;
}

// ---------------- tf32 helpers ----------------
__device__ __forceinline__ uint32_t f2tf(float f) {
    uint32_t u;
    asm("cvt.rna.tf32.f32 %0, %1;" : "=r"(u) : "f"(f));
    return u;
}

__device__ __forceinline__ void mma8(float* d, const uint32_t* a, uint32_t b0, uint32_t b1) {
    asm volatile(
        "mma.sync.aligned.m16n8k8.row.col.f32.tf32.tf32.f32 "
        "{%0,%1,%2,%3},{%4,%5,%6,%7},{%8,%9},{%0,%1,%2,%3};"
        : "+f"(d[0]), "+f"(d[1]), "+f"(d[2]), "+f"(d[3])
        : "r"(a[0]), "r"(a[1]), "r"(a[2]), "r"(a[3]), "r"(b0), "r"(b1));
}

// ---------------- one-time W -> tf32 hi/lo fragment conversion (all 3 layers) ----------------
__global__ void k_wconv(const float* __restrict__ W1,
                        const float* __restrict__ W2,
                        const float* __restrict__ W3) {
    int e = blockIdx.x * blockDim.x + threadIdx.x;
    if (e >= 3 * 16384) return;
    int l = e >> 14;
    int f = e & 16383;
    const float* W = (l == 0) ? W1 : (l == 1 ? W2 : W3);
    int j  = f & 1;
    int ln = (f >> 1) & 31;
    int KS = (f >> 6) & 15;
    int NT = f >> 10;
    int k = KS * 8 + (ln & 3) + 4 * j;
    int n = NT * 8 + (ln >> 2);
    float v = W[k * 128 + n];
    uint32_t hi = f2tf(v);
    g_Bh[e] = hi;
    g_Bl[e] = f2tf(v - __uint_as_float(hi));
}

// ---------------- tensor-core GEMM: g_T[M,128] = (A[M,128] @ W[128,128]) * dinv[row], fp16 ----
template<int SRC, int L>
__global__ void __launch_bounds__(512, 2) k_gemm_tc(const float* __restrict__ Aext) {
    extern __shared__ uint32_t sb[];      // sBh[8192], sBl[8192]
    uint32_t* sBh = sb;
    uint32_t* sBl = sb + 8192;
    const float* A = (SRC == 0) ? Aext : (SRC == 1 ? (const float*)g_H0 : (const float*)g_H1);
    const int tid = threadIdx.x;
    const int nhalf = blockIdx.x & 1;
    const int mblk  = blockIdx.x >> 1;

    {
        const uint4* srcH = (const uint4*)(g_Bh + L * 16384 + nhalf * 8192);
        const uint4* srcL = (const uint4*)(g_Bl + L * 16384 + nhalf * 8192);
        uint4* dH = (uint4*)sBh;
        uint4* dL = (uint4*)sBl;
        for (int i = tid; i < 2048; i += 512) { dH[i] = srcH[i]; dL[i] = srcL[i]; }
    }
    __syncthreads();

    const int wid = tid >> 5, lane = tid & 31;
    const int g = lane >> 2, t4 = lane & 3;
    const int m_base = mblk * 256 + wid * 16;
    const int r0 = m_base + g, r1 = r0 + 8;
    const bool v0 = r0 < NN, v1 = r1 < NN;
    const float* A0 = A + (size_t)r0 * 128;
    const float* A1 = A + (size_t)r1 * 128;

    float acc[8][4];
#pragma unroll
    for (int nt = 0; nt < 8; nt++)
#pragma unroll
        for (int q = 0; q < 4; q++) acc[nt][q] = 0.f;

#pragma unroll
    for (int ks = 0; ks < 16; ks++) {
        const int k0 = ks * 8 + t4;
        float fv[4];
        fv[0] = v0 ? A0[k0]     : 0.f;
        fv[1] = v1 ? A1[k0]     : 0.f;
        fv[2] = v0 ? A0[k0 + 4] : 0.f;
        fv[3] = v1 ? A1[k0 + 4] : 0.f;
        uint32_t ah[4], al[4];
#pragma unroll
        for (int q = 0; q < 4; q++) {
            uint32_t hi = f2tf(fv[q]);
            ah[q] = hi;
            al[q] = f2tf(fv[q] - __uint_as_float(hi));
        }

#pragma unroll
        for (int nt = 0; nt < 8; nt++) {
            int base = ((nt * 16 + ks) * 32 + lane) * 2;
            uint32_t bh0 = sBh[base], bh1 = sBh[base + 1];
            uint32_t bl0 = sBl[base], bl1 = sBl[base + 1];
            mma8(acc[nt], ah, bh0, bh1);
            mma8(acc[nt], al, bh0, bh1);
            mma8(acc[nt], ah, bl0, bl1);
        }
    }

    // Epilogue: T' = acc * dinv[row], stored fp16 (half2 per 2 cols)
    float dv0 = v0 ? g_dinv[r0] : 0.f;
    float dv1 = v1 ? g_dinv[r1] : 0.f;
#pragma unroll
    for (int nt = 0; nt < 8; nt++) {
        int col = nhalf * 64 + nt * 8 + t4 * 2;
        if (v0) *(__half2*)(g_T + (size_t)r0 * 128 + col) =
            __floats2half2_rn(acc[nt][0] * dv0, acc[nt][1] * dv0);
        if (v1) *(__half2*)(g_T + (size_t)r1 * 128 + col) =
            __floats2half2_rn(acc[nt][2] * dv1, acc[nt][3] * dv1);
    }
}

// ---------------- gather: out[d] = dinv[d]*(T'[d] + sum_e T'[src_e]) + b ----------------
// One warp per dst node; fp16 T reads (8B/lane); relu on store; POOL fuses graph-sum.
__device__ __forceinline__ void h4acc(float4& acc, uint2 h4) {
    __half2 p0 = *(__half2*)&h4.x;
    __half2 p1 = *(__half2*)&h4.y;
    float2 f0 = __half22float2(p0);
    float2 f1 = __half22float2(p1);
    acc.x += f0.x; acc.y += f0.y; acc.z += f1.x; acc.w += f1.y;
}

template<int DST, bool POOL>
__global__ void __launch_bounds__(256) k_gather(const float* __restrict__ b,
                                                const void* __restrict__ batch) {
    float* O = (DST == 1) ? g_H0 : g_H1;
    int node = (blockIdx.x * blockDim.x + threadIdx.x) >> 5;
    int lane = threadIdx.x & 31;
    if (node >= NN) return;
    int c = lane * 4;
    const uint2* Tb = (const uint2*)g_T;   // 4 halves per uint2; row stride = 32 uint2

    float4 acc = make_float4(0.f, 0.f, 0.f, 0.f);
    h4acc(acc, Tb[(size_t)node * 32 + lane]);          // self loop T'[d]

    int e = g_start[node];
    int end = e + g_degi[node];
    // 4-way unrolled for index/feature MLP
    for (; e + 4 <= end; e += 4) {
        int s0 = g_csrc[e], s1 = g_csrc[e + 1], s2 = g_csrc[e + 2], s3 = g_csrc[e + 3];
        uint2 v0 = Tb[(size_t)s0 * 32 + lane];
        uint2 v1 = Tb[(size_t)s1 * 32 + lane];
        uint2 v2 = Tb[(size_t)s2 * 32 + lane];
        uint2 v3 = Tb[(size_t)s3 * 32 + lane];
        h4acc(acc, v0); h4acc(acc, v1); h4acc(acc, v2); h4acc(acc, v3);
    }
    for (; e < end; e++) {
        h4acc(acc, Tb[(size_t)g_csrc[e] * 32 + lane]);
    }

    float dv = g_dinv[node];
    float4 bb = *(const float4*)(b + c);
    acc.x = fmaf(acc.x, dv, bb.x);
    acc.y = fmaf(acc.y, dv, bb.y);
    acc.z = fmaf(acc.z, dv, bb.z);
    acc.w = fmaf(acc.w, dv, bb.w);
    // relu (reference applies relu after every conv, including before pooling)
    acc.x = fmaxf(acc.x, 0.f); acc.y = fmaxf(acc.y, 0.f);
    acc.z = fmaxf(acc.z, 0.f); acc.w = fmaxf(acc.w, 0.f);

    if (POOL) {
        int gph = batch_at(batch, node);
        float* p = g_sums + gph * 128 + c;
        atomicAdd(p + 0, acc.x);
        atomicAdd(p + 1, acc.y);
        atomicAdd(p + 2, acc.z);
        atomicAdd(p + 3, acc.w);
        if (lane == 0) atomicAdd(&g_cnt[gph], 1);
    } else {
        *(float4*)(O + (size_t)node * 128 + c) = acc;
    }
}

// ---------------- head: out[g] = relu(mean @ Wf1 + bf1) @ Wf2 + bf2 ----------------
__global__ void __launch_bounds__(64) k_head(const float* __restrict__ Wf1,
                                             const float* __restrict__ bf1,
                                             const float* __restrict__ Wf2,
                                             const float* __restrict__ bf2,
                                             float* __restrict__ out) {
    int g = blockIdx.x;
    int j = threadIdx.x;
    __shared__ float hg[128];
    __shared__ float red[2];
    float invc = 1.f / fmaxf((float)g_cnt[g], 1.f);
    for (int k = j; k < 128; k += 64) hg[k] = g_sums[g * 128 + k] * invc;
    __syncthreads();
    float acc = bf1[j];
#pragma unroll
    for (int k = 0; k < 128; k++) acc = fmaf(hg[k], Wf1[k * 64 + j], acc);
    acc = fmaxf(acc, 0.f) * Wf2[j];
#pragma unroll
    for (int off = 16; off; off >>= 1) acc += __shfl_down_sync(0xffffffffu, acc, off);
    if ((j & 31) == 0) red[j >> 5] = acc;
    __syncthreads();
    if (j == 0) out[g] = red[0] + red[1] + bf2[0];
}

// ---------------- launch ----------------
extern "C" void kernel_launch(void* const* d_in, const int* in_sizes, int n_in,
                              void* d_out, int out_size) {
    const float* x    = (const float*)d_in[0];
    const void*  edge = d_in[1];
    const void*  bat  = d_in[2];
    const float* W1 = (const float*)d_in[3];
    const float* b1 = (const float*)d_in[4];
    const float* W2 = (const float*)d_in[5];
    const float* b2 = (const float*)d_in[6];
    const float* W3 = (const float*)d_in[7];
    const float* b3 = (const float*)d_in[8];
    const float* Wf1 = (const float*)d_in[9];
    const float* bf1 = (const float*)d_in[10];
    const float* Wf2 = (const float*)d_in[11];
    const float* bf2 = (const float*)d_in[12];
    float* out = (float*)d_out;

    const int SMEM = 65536;   // sBh + sBl
    cudaFuncSetAttribute(k_gemm_tc<0, 0>, cudaFuncAttributeMaxDynamicSharedMemorySize, SMEM);
    cudaFuncSetAttribute(k_gemm_tc<1, 1>, cudaFuncAttributeMaxDynamicSharedMemorySize, SMEM);
    cudaFuncSetAttribute(k_gemm_tc<2, 2>, cudaFuncAttributeMaxDynamicSharedMemorySize, SMEM);

    const int TPB = 256;
    k_detect<<<1, 512>>>(edge, bat);
    k_zero<<<(NG * F + TPB - 1) / TPB, TPB>>>();
    k_deg <<<(NE + TPB - 1) / TPB, TPB>>>(edge);
    k_scan1<<<NB, 256>>>();
    k_scan2<<<1, 256>>>();
    k_scan3<<<NB, 256>>>();
    k_fill<<<(NE + TPB - 1) / TPB, TPB>>>(edge);
    k_wconv<<<192, 256>>>(W1, W2, W3);

    const int gemmGrid = 2 * ((NN + 255) / 256);   // 392
    const int gathGrid = (int)(((long long)NN * 32 + TPB - 1) / TPB);

    // layer 1: x -> H0
    k_gemm_tc<0, 0><<<gemmGrid, 512, SMEM>>>(x);
    k_gather<1, false><<<gathGrid, TPB>>>(b1, nullptr);
    // layer 2: H0 -> H1
    k_gemm_tc<1, 1><<<gemmGrid, 512, SMEM>>>(nullptr);
    k_gather<2, false><<<gathGrid, TPB>>>(b2, nullptr);
    // layer 3: H1 -> (pool fused)
    k_gemm_tc<2, 2><<<gemmGrid, 512, SMEM>>>(nullptr);
    k_gather<1, true><<<gathGrid, TPB>>>(b3, bat);

    k_head<<<NG, 64>>>(Wf1, bf1, Wf2, bf2, out);
}

// round 16
// speedup vs baseline: 4.1737x; 1.2446x over previous
#include <cuda_runtime.h>
#include <cuda_fp16.h>
#include <cstdint>

#define NN 50000
#define NE 600000
#define NG 500
#define F  128
#define NB 196   // (NN+255)/256

// ---------------- scratch (static __device__, no allocation) ----------------
__device__ __align__(16) __half g_T [NN * F];  // T' = (A@W)*dinv[row], fp16
__device__ __align__(16) __half g_X [NN * F];  // x converted to fp16
__device__ __align__(16) __half g_H0[NN * F];  // layer outputs (ping), post-relu, fp16
__device__ __align__(16) __half g_H1[NN * F];  // layer outputs (pong), post-relu, fp16
__device__ int   g_degi[NN];
__device__ float g_dinv[NN];
__device__ int   g_tmp [NN];
__device__ int   g_bsum[256];
__device__ int   g_boff[256];
__device__ int   g_start[NN];
__device__ int   g_cur [NN];
__device__ int   g_csrc[NE];
__device__ __align__(16) float g_sums[NG * F];
__device__ int   g_cnt [NG];
__device__ int   g_e64;
__device__ int   g_b64;
// fp16 W fragments: [layer][nhalf][nt(8)][ks(8)][lane(32)][reg(2)] -> 8192 u32 per layer
__device__ __align__(16) uint32_t g_Wh[3 * 8192];
__device__ __align__(16) uint32_t g_Wl[3 * 8192];

// ---------------- dtype detection ----------------
__global__ void k_detect(const void* edge, const void* batch) {
    __shared__ int bad[2];
    int t = threadIdx.x;
    if (t < 2) bad[t] = 0;
    __syncthreads();
    if (t < 256) {
        long long v = ((const long long*)edge)[t];
        if (v < 0 || v >= NN) bad[0] = 1;
    } else {
        long long v = ((const long long*)batch)[t - 256];
        if (v < 0 || v >= NG) bad[1] = 1;
    }
    __syncthreads();
    if (t == 0) { g_e64 = !bad[0]; g_b64 = !bad[1]; }
}

__device__ __forceinline__ int edge_at(const void* edge, long long idx) {
    return g_e64 ? (int)((const long long*)edge)[idx] : ((const int*)edge)[idx];
}
__device__ __forceinline__ int batch_at(const void* batch, int idx) {
    return g_b64 ? (int)((const long long*)batch)[idx] : ((const int*)batch)[idx];
}

// ---------------- prep ----------------
__global__ void k_zero() {
    int i = blockIdx.x * blockDim.x + threadIdx.x;
    if (i < NN) g_degi[i] = 0;
    if (i < NG * F) g_sums[i] = 0.f;
    if (i < NG) g_cnt[i] = 0;
}

__global__ void k_deg(const void* __restrict__ edge) {
    int i = blockIdx.x * blockDim.x + threadIdx.x;
    if (i >= NE) return;
    int d = edge_at(edge, (long long)NE + i);
    atomicAdd(&g_degi[d], 1);
}

__global__ void k_scan1() {
    __shared__ int s[256];
    int b = blockIdx.x, t = threadIdx.x;
    int i = b * 256 + t;
    int v = (i < NN) ? g_degi[i] : 0;
    s[t] = v; __syncthreads();
#pragma unroll
    for (int off = 1; off < 256; off <<= 1) {
        int x = 0;
        if (t >= off) x = s[t - off];
        __syncthreads();
        if (t >= off) s[t] += x;
        __syncthreads();
    }
    if (i < NN) g_tmp[i] = s[t];
    if (t == 255) g_bsum[b] = s[255];
}

__global__ void k_scan2() {
    __shared__ int s[256];
    int t = threadIdx.x;
    int v = (t < NB) ? g_bsum[t] : 0;
    s[t] = v; __syncthreads();
#pragma unroll
    for (int off = 1; off < 256; off <<= 1) {
        int x = 0;
        if (t >= off) x = s[t - off];
        __syncthreads();
        if (t >= off) s[t] += x;
        __syncthreads();
    }
    g_boff[t] = s[t] - v;
}

__global__ void k_scan3() {
    int i = blockIdx.x * blockDim.x + threadIdx.x;
    if (i >= NN) return;
    int deg = g_degi[i];
    int start = g_tmp[i] - deg + g_boff[i >> 8];
    g_start[i] = start;
    g_cur[i] = start;
    g_dinv[i] = rsqrtf((float)(deg + 1));
}

__global__ void k_fill(const void* __restrict__ edge) {
    int i = blockIdx.x * blockDim.x + threadIdx.x;
    if (i >= NE) return;
    int s = edge_at(edge, i);
    int d = edge_at(edge, (long long)NE + i);
    int pos = atomicAdd(&g_cur[d], 1);
    g_csrc[pos] = s;
}

// ---------------- x -> fp16 (float4 in, half2x4 out) ----------------
__global__ void k_xconv(const float* __restrict__ x) {
    int i = blockIdx.x * blockDim.x + threadIdx.x;   // uint of 4 floats
    if (i >= NN * F / 4) return;
    float4 v = *(const float4*)(x + (size_t)i * 4);
    uint2 o;
    *(__half2*)&o.x = __floats2half2_rn(v.x, v.y);
    *(__half2*)&o.y = __floats2half2_rn(v.z, v.w);
    *(uint2*)(g_X + (size_t)i * 4) = o;
}

// ---------------- one-time W -> fp16 hi/lo fragments (m16n8k16 layout) ----------------
// frag e (per layer): ((NT*8 + ks)*32 + lane)*2 + j  holds half2 {W[k][n], W[k+1][n]}
//   k = ks*16 + 2*(lane&3) + 8*j ; n = NT*8 + (lane>>2) ; NT in 0..15
__global__ void k_wconv(const float* __restrict__ W1,
                        const float* __restrict__ W2,
                        const float* __restrict__ W3) {
    int e = blockIdx.x * blockDim.x + threadIdx.x;
    if (e >= 3 * 8192) return;
    int l = e / 8192;
    int f = e & 8191;
    const float* W = (l == 0) ? W1 : (l == 1 ? W2 : W3);
    int j  = f & 1;
    int ln = (f >> 1) & 31;
    int ks = (f >> 6) & 7;
    int NT = f >> 9;
    int k = ks * 16 + 2 * (ln & 3) + 8 * j;
    int n = NT * 8 + (ln >> 2);
    float v0 = W[k * 128 + n];
    float v1 = W[(k + 1) * 128 + n];
    __half h0 = __float2half_rn(v0);
    __half h1 = __float2half_rn(v1);
    __half l0 = __float2half_rn(v0 - __half2float(h0));
    __half l1 = __float2half_rn(v1 - __half2float(h1));
    uint32_t uh, ul;
    *(__half2*)&uh = __halves2half2(h0, h1);
    *(__half2*)&ul = __halves2half2(l0, l1);
    g_Wh[e] = uh;
    g_Wl[e] = ul;
}

// ---------------- fp16 mma helpers ----------------
__device__ __forceinline__ void mma16(float* d, const uint32_t* a, uint32_t b0, uint32_t b1) {
    asm volatile(
        "mma.sync.aligned.m16n8k16.row.col.f32.f16.f16.f32 "
        "{%0,%1,%2,%3},{%4,%5,%6,%7},{%8,%9},{%0,%1,%2,%3};"
        : "+f"(d[0]), "+f"(d[1]), "+f"(d[2]), "+f"(d[3])
        : "r"(a[0]), "r"(a[1]), "r"(a[2]), "r"(a[3]), "r"(b0), "r"(b1));
}

// ---------------- tensor-core GEMM: g_T = (A_fp16 @ (Wh+Wl)) * dinv[row], fp16 out ----------
// Block = 512 thr = 16 warps, one m16 band each; BM=256, BN=64 (nhalf). A exact fp16.
template<int SRC, int L>
__global__ void __launch_bounds__(512, 2) k_gemm_tc() {
    extern __shared__ uint32_t sb[];      // sWh[4096], sWl[4096]  (32 KB)
    uint32_t* sWh = sb;
    uint32_t* sWl = sb + 4096;
    const __half* A = (SRC == 0) ? g_X : (SRC == 1 ? g_H0 : g_H1);
    const int tid = threadIdx.x;
    const int nhalf = blockIdx.x & 1;
    const int mblk  = blockIdx.x >> 1;

    {
        const uint4* srcH = (const uint4*)(g_Wh + L * 8192 + nhalf * 4096);
        const uint4* srcL = (const uint4*)(g_Wl + L * 8192 + nhalf * 4096);
        uint4* dH = (uint4*)sWh;
        uint4* dL = (uint4*)sWl;
        for (int i = tid; i < 1024; i += 512) { dH[i] = srcH[i]; dL[i] = srcL[i]; }
    }
    __syncthreads();

    const int wid = tid >> 5, lane = tid & 31;
    const int g = lane >> 2, t4 = lane & 3;
    const int m_base = mblk * 256 + wid * 16;
    const int r0 = m_base + g, r1 = r0 + 8;
    const bool v0 = r0 < NN, v1 = r1 < NN;
    const __half* A0 = A + (size_t)r0 * 128;
    const __half* A1 = A + (size_t)r1 * 128;

    float acc[8][4];
#pragma unroll
    for (int nt = 0; nt < 8; nt++)
#pragma unroll
        for (int q = 0; q < 4; q++) acc[nt][q] = 0.f;

#pragma unroll
    for (int ks = 0; ks < 8; ks++) {
        const int k0 = ks * 16 + 2 * t4;
        uint32_t a[4];
        a[0] = v0 ? *(const uint32_t*)(A0 + k0)     : 0u;
        a[1] = v1 ? *(const uint32_t*)(A1 + k0)     : 0u;
        a[2] = v0 ? *(const uint32_t*)(A0 + k0 + 8) : 0u;
        a[3] = v1 ? *(const uint32_t*)(A1 + k0 + 8) : 0u;

#pragma unroll
        for (int nt = 0; nt < 8; nt++) {
            int base = ((nt * 8 + ks) * 32 + lane) * 2;
            uint32_t bh0 = sWh[base], bh1 = sWh[base + 1];
            uint32_t bl0 = sWl[base], bl1 = sWl[base + 1];
            mma16(acc[nt], a, bh0, bh1);
            mma16(acc[nt], a, bl0, bl1);
        }
    }

    float dv0 = v0 ? g_dinv[r0] : 0.f;
    float dv1 = v1 ? g_dinv[r1] : 0.f;
#pragma unroll
    for (int nt = 0; nt < 8; nt++) {
        int col = nhalf * 64 + nt * 8 + t4 * 2;
        if (v0) *(__half2*)(g_T + (size_t)r0 * 128 + col) =
            __floats2half2_rn(acc[nt][0] * dv0, acc[nt][1] * dv0);
        if (v1) *(__half2*)(g_T + (size_t)r1 * 128 + col) =
            __floats2half2_rn(acc[nt][2] * dv1, acc[nt][3] * dv1);
    }
}

// ---------------- gather: out[d] = relu(dinv[d]*(T'[d] + sum_e T'[src_e]) + b) ----------------
__device__ __forceinline__ void h4acc(float4& acc, uint2 h4) {
    float2 f0 = __half22float2(*(__half2*)&h4.x);
    float2 f1 = __half22float2(*(__half2*)&h4.y);
    acc.x += f0.x; acc.y += f0.y; acc.z += f1.x; acc.w += f1.y;
}

template<int DST, bool POOL>
__global__ void __launch_bounds__(256) k_gather(const float* __restrict__ b,
                                                const void* __restrict__ batch) {
    __half* O = (DST == 1) ? g_H0 : g_H1;
    int node = (blockIdx.x * blockDim.x + threadIdx.x) >> 5;
    int lane = threadIdx.x & 31;
    if (node >= NN) return;
    int c = lane * 4;
    const uint2* Tb = (const uint2*)g_T;   // 4 halves per uint2; row stride 32

    float4 acc = make_float4(0.f, 0.f, 0.f, 0.f);
    h4acc(acc, Tb[(size_t)node * 32 + lane]);          // self loop

    int e = g_start[node];
    int end = e + g_degi[node];
    for (; e + 4 <= end; e += 4) {
        int s0 = g_csrc[e], s1 = g_csrc[e + 1], s2 = g_csrc[e + 2], s3 = g_csrc[e + 3];
        uint2 v0 = Tb[(size_t)s0 * 32 + lane];
        uint2 v1 = Tb[(size_t)s1 * 32 + lane];
        uint2 v2 = Tb[(size_t)s2 * 32 + lane];
        uint2 v3 = Tb[(size_t)s3 * 32 + lane];
        h4acc(acc, v0); h4acc(acc, v1); h4acc(acc, v2); h4acc(acc, v3);
    }
    for (; e < end; e++) h4acc(acc, Tb[(size_t)g_csrc[e] * 32 + lane]);

    float dv = g_dinv[node];
    float4 bb = *(const float4*)(b + c);
    acc.x = fmaxf(fmaf(acc.x, dv, bb.x), 0.f);
    acc.y = fmaxf(fmaf(acc.y, dv, bb.y), 0.f);
    acc.z = fmaxf(fmaf(acc.z, dv, bb.z), 0.f);
    acc.w = fmaxf(fmaf(acc.w, dv, bb.w), 0.f);

    if (POOL) {
        int gph = batch_at(batch, node);
        float* p = g_sums + gph * 128 + c;
        atomicAdd(p + 0, acc.x);
        atomicAdd(p + 1, acc.y);
        atomicAdd(p + 2, acc.z);
        atomicAdd(p + 3, acc.w);
        if (lane == 0) atomicAdd(&g_cnt[gph], 1);
    } else {
        uint2 o;
        *(__half2*)&o.x = __floats2half2_rn(acc.x, acc.y);
        *(__half2*)&o.y = __floats2half2_rn(acc.z, acc.w);
        *(uint2*)(O + (size_t)node * 128 + c) = o;
    }
}

// ---------------- head ----------------
__global__ void __launch_bounds__(64) k_head(const float* __restrict__ Wf1,
                                             const float* __restrict__ bf1,
                                             const float* __restrict__ Wf2,
                                             const float* __restrict__ bf2,
                                             float* __restrict__ out) {
    int g = blockIdx.x;
    int j = threadIdx.x;
    __shared__ float hg[128];
    __shared__ float red[2];
    float invc = 1.f / fmaxf((float)g_cnt[g], 1.f);
    for (int k = j; k < 128; k += 64) hg[k] = g_sums[g * 128 + k] * invc;
    __syncthreads();
    float acc = bf1[j];
#pragma unroll
    for (int k = 0; k < 128; k++) acc = fmaf(hg[k], Wf1[k * 64 + j], acc);
    acc = fmaxf(acc, 0.f) * Wf2[j];
#pragma unroll
    for (int off = 16; off; off >>= 1) acc += __shfl_down_sync(0xffffffffu, acc, off);
    if ((j & 31) == 0) red[j >> 5] = acc;
    __syncthreads();
    if (j == 0) out[g] = red[0] + red[1] + bf2[0];
}

// ---------------- launch ----------------
extern "C" void kernel_launch(void* const* d_in, const int* in_sizes, int n_in,
                              void* d_out, int out_size) {
    const float* x    = (const float*)d_in[0];
    const void*  edge = d_in[1];
    const void*  bat  = d_in[2];
    const float* W1 = (const float*)d_in[3];
    const float* b1 = (const float*)d_in[4];
    const float* W2 = (const float*)d_in[5];
    const float* b2 = (const float*)d_in[6];
    const float* W3 = (const float*)d_in[7];
    const float* b3 = (const float*)d_in[8];
    const float* Wf1 = (const float*)d_in[9];
    const float* bf1 = (const float*)d_in[10];
    const float* Wf2 = (const float*)d_in[11];
    const float* bf2 = (const float*)d_in[12];
    float* out = (float*)d_out;

    const int SMEM = 32768;   // sWh + sWl
    cudaFuncSetAttribute(k_gemm_tc<0, 0>, cudaFuncAttributeMaxDynamicSharedMemorySize, SMEM);
    cudaFuncSetAttribute(k_gemm_tc<1, 1>, cudaFuncAttributeMaxDynamicSharedMemorySize, SMEM);
    cudaFuncSetAttribute(k_gemm_tc<2, 2>, cudaFuncAttributeMaxDynamicSharedMemorySize, SMEM);

    const int TPB = 256;
    k_detect<<<1, 512>>>(edge, bat);
    k_zero<<<(NG * F + TPB - 1) / TPB, TPB>>>();
    k_deg <<<(NE + TPB - 1) / TPB, TPB>>>(edge);
    k_scan1<<<NB, 256>>>();
    k_scan2<<<1, 256>>>();
    k_scan3<<<NB, 256>>>();
    k_fill<<<(NE + TPB - 1) / TPB, TPB>>>(edge);
    k_xconv<<<(NN * F / 4 + TPB - 1) / TPB, TPB>>>(x);
    k_wconv<<<96, 256>>>(W1, W2, W3);

    const int gemmGrid = 2 * ((NN + 255) / 256);   // 392
    const int gathGrid = (int)(((long long)NN * 32 + TPB - 1) / TPB);

    // layer 1: X -> H0
    k_gemm_tc<0, 0><<<gemmGrid, 512, SMEM>>>();
    k_gather<1, false><<<gathGrid, TPB>>>(b1, nullptr);
    // layer 2: H0 -> H1
    k_gemm_tc<1, 1><<<gemmGrid, 512, SMEM>>>();
    k_gather<2, false><<<gathGrid, TPB>>>(b2, nullptr);
    // layer 3: H1 -> (pool fused)
    k_gemm_tc<2, 2><<<gemmGrid, 512, SMEM>>>();
    k_gather<1, true><<<gathGrid, TPB>>>(b3, bat);

    k_head<<<NG, 64>>>(Wf1, bf1, Wf2, bf2, out);
}